// round 10
// baseline (speedup 1.0000x reference)
#include <cuda_runtime.h>
#include <cuda_fp16.h>
#include <math.h>
#include <stdint.h>

#define B_    4096
#define C_    6
#define L_    1024
#define MID_  512
#define HID_  512
#define OUT_  256
#define K_    5
#define NBIG  5632
#define MROWS (B_ * C_)
#define KCDD  128              /* dedup k-chunks: hi [0,64) + lo [64,128) */

#define TM 128
#define TN 256
#define NSTG 48
#define ASTG_BYTES 16384
#define STG_BYTES  49152
#define SMEM_TOTAL (4 * STG_BYTES)

__device__ uint4 g_Ah[(size_t)(MROWS / 16) * KCDD * 32];   /* 100 MB */
__device__ uint4 g_Bh[(size_t)(NBIG / 16) * KCDD * 32];    /*  23 MB */
__device__ float g_Y[(size_t)MROWS * NBIG];
__device__ float g_A[(size_t)B_ * 36];
__device__ float g_HG[(size_t)MROWS * OUT_];

__device__ __forceinline__ uint32_t smem_u32(const void* p) {
    uint32_t a;
    asm("{ .reg .u64 t; cvta.to.shared.u64 t, %1; cvt.u32.u64 %0, t; }" : "=r"(a) : "l"(p));
    return a;
}
__device__ __forceinline__ void cpa16(uint32_t s, const void* g) {
    asm volatile("cp.async.cg.shared.global [%0], [%1], 16;" :: "r"(s), "l"(g) : "memory");
}
__device__ __forceinline__ void lds128(uint32_t* r, uint32_t a) {
    asm volatile("ld.shared.v4.b32 {%0,%1,%2,%3}, [%4];"
                 : "=r"(r[0]), "=r"(r[1]), "=r"(r[2]), "=r"(r[3]) : "r"(a));
}
__device__ __forceinline__ void mma_f16(float* c, const uint32_t* a, uint32_t b0, uint32_t b1) {
    asm volatile(
        "mma.sync.aligned.m16n8k16.row.col.f32.f16.f16.f32 "
        "{%0,%1,%2,%3}, {%4,%5,%6,%7}, {%8,%9}, {%0,%1,%2,%3};"
        : "+f"(c[0]), "+f"(c[1]), "+f"(c[2]), "+f"(c[3])
        : "r"(a[0]), "r"(a[1]), "r"(a[2]), "r"(a[3]), "r"(b0), "r"(b1));
}
__device__ __forceinline__ __half cvt_split(float x, bool lo) {
    __half hi = __float2half_rn(x);
    if (!lo) return hi;
    return __float2half_rn(x - __half2float(hi));
}

/* ------------------------- packs (dedup) -------------------------- */
__global__ void packA_kernel(const float* __restrict__ X) {
    int cid = blockIdx.x * 256 + threadIdx.x;
    int ln = cid & 31;
    int b = cid >> 5;
    int kc = b & (KCDD - 1);
    int mt = b >> 7;
    bool lo = kc >= 64;
    int l0 = (kc & 63) * 16 + (ln & 3) * 2;
    int r0 = mt * 16 + (ln >> 2);
    float2 x00 = *(const float2*)(X + (size_t)r0 * L_ + l0);
    float2 x10 = *(const float2*)(X + (size_t)(r0 + 8) * L_ + l0);
    float2 x01 = *(const float2*)(X + (size_t)r0 * L_ + l0 + 8);
    float2 x11 = *(const float2*)(X + (size_t)(r0 + 8) * L_ + l0 + 8);
    __half h[8];
    h[0] = cvt_split(x00.x, lo); h[1] = cvt_split(x00.y, lo);
    h[2] = cvt_split(x10.x, lo); h[3] = cvt_split(x10.y, lo);
    h[4] = cvt_split(x01.x, lo); h[5] = cvt_split(x01.y, lo);
    h[6] = cvt_split(x11.x, lo); h[7] = cvt_split(x11.y, lo);
    g_Ah[cid] = *(uint4*)h;
}
__device__ __forceinline__ float fetchW(const float* aW1, const float* aW2,
                                        const float* gW1, int l, int n) {
    if (n < K_ * MID_) {
        return aW1[((size_t)(n >> 9) * L_ + l) * MID_ + (n & 511)];
    } else if (n < 2 * K_ * MID_) {
        int nn = n - K_ * MID_;
        return aW2[((size_t)(nn >> 9) * L_ + l) * MID_ + (nn & 511)];
    }
    return gW1[(size_t)l * HID_ + (n - 2 * K_ * MID_)];
}
__global__ void packB_kernel(const float* __restrict__ aW1,
                             const float* __restrict__ aW2,
                             const float* __restrict__ gW1) {
    int cid = blockIdx.x * 256 + threadIdx.x;
    int ln = cid & 31;
    int b = cid >> 5;
    int kc = b & (KCDD - 1);
    int nt = b >> 7;
    bool lo = kc >= 64;
    int l0 = (kc & 63) * 16 + (ln & 3) * 2;
    int n0 = nt * 16 + (ln >> 2);
    int n1 = n0 + 8;
    __half h[8];
    h[0] = cvt_split(fetchW(aW1, aW2, gW1, l0,     n0), lo);
    h[1] = cvt_split(fetchW(aW1, aW2, gW1, l0 + 1, n0), lo);
    h[2] = cvt_split(fetchW(aW1, aW2, gW1, l0 + 8, n0), lo);
    h[3] = cvt_split(fetchW(aW1, aW2, gW1, l0 + 9, n0), lo);
    h[4] = cvt_split(fetchW(aW1, aW2, gW1, l0,     n1), lo);
    h[5] = cvt_split(fetchW(aW1, aW2, gW1, l0 + 1, n1), lo);
    h[6] = cvt_split(fetchW(aW1, aW2, gW1, l0 + 8, n1), lo);
    h[7] = cvt_split(fetchW(aW1, aW2, gW1, l0 + 9, n1), lo);
    g_Bh[cid] = *(uint4*)h;
}

/* ------------------ big GEMM (dedup stage remap) ------------------ */
struct IssueCtx { uint32_t sb; int mtB, ntB, tid; };

__device__ __forceinline__ void issue_stage(const IssueCtx& cx, int s) {
    uint32_t stBase = cx.sb + (s & 3) * STG_BYTES;
    int akc0 = (s < 16) ? s * 4 : (s < 32) ? 64 + (s - 16) * 4 : (s - 32) * 4;
    int bkc0 = (s < 16) ? s * 4 : (s < 32) ? (s - 16) * 4 : 64 + (s - 32) * 4;
#pragma unroll
    for (int i = 0; i < 4; i++) {
        int cid = cx.tid + i * 256;
        int ln = cid & 31, bb = cid >> 5;
        int kci = bb >> 3, mti = bb & 7;
        uint32_t sa = stBase + (uint32_t)(((kci * 8 + mti) * 32 + ln) * 16);
        const uint4* ga = g_Ah + ((size_t)(cx.mtB + mti) * KCDD + akc0 + kci) * 32 + ln;
        cpa16(sa, ga);
    }
#pragma unroll
    for (int i = 0; i < 8; i++) {
        int cid = cx.tid + i * 256;
        int ln = cid & 31, bb = cid >> 5;
        int kci = bb >> 4, nti = bb & 15;
        uint32_t sb2 = stBase + ASTG_BYTES + (uint32_t)(((kci * 16 + nti) * 32 + ln) * 16);
        const uint4* gb = g_Bh + ((size_t)(cx.ntB + nti) * KCDD + bkc0 + kci) * 32 + ln;
        cpa16(sb2, gb);
    }
    asm volatile("cp.async.commit_group;" ::: "memory");
}

__global__ void __launch_bounds__(256, 1) gemm_kernel() {
    extern __shared__ char smem[];
    const uint32_t sb = smem_u32(smem);
    const int tid = threadIdx.x;
    const int lane = tid & 31;
    const int wid = tid >> 5;
    const int wm = wid & 1;
    const int wn = wid >> 1;
    const int mtB = blockIdx.y * 8;
    const int ntB = blockIdx.x * 16;

    IssueCtx cx{sb, mtB, ntB, tid};

    float acc[4][8][4];
#pragma unroll
    for (int a = 0; a < 4; a++)
#pragma unroll
        for (int bq = 0; bq < 8; bq++)
#pragma unroll
            for (int c = 0; c < 4; c++) acc[a][bq][c] = 0.f;

    issue_stage(cx, 0);
    issue_stage(cx, 1);
    issue_stage(cx, 2);

    for (int s = 0; s < NSTG; s++) {
        asm volatile("cp.async.wait_group 2;" ::: "memory");
        __syncthreads();
        if (s + 3 < NSTG) issue_stage(cx, s + 3);
        else asm volatile("cp.async.commit_group;" ::: "memory");

        uint32_t stBase = sb + (s & 3) * STG_BYTES;
#pragma unroll
        for (int kc = 0; kc < 4; kc++) {
            uint32_t af[4][4], bf[4][4];
#pragma unroll
            for (int mi = 0; mi < 4; mi++)
                lds128(af[mi], stBase + (uint32_t)((((kc * 8) + wm * 4 + mi) * 32 + lane) * 16));
#pragma unroll
            for (int ni = 0; ni < 4; ni++)
                lds128(bf[ni], stBase + ASTG_BYTES +
                               (uint32_t)((((kc * 16) + wn * 4 + ni) * 32 + lane) * 16));
#pragma unroll
            for (int mi = 0; mi < 4; mi++)
#pragma unroll
                for (int ni = 0; ni < 4; ni++) {
                    mma_f16(acc[mi][ni * 2],     af[mi], bf[ni][0], bf[ni][1]);
                    mma_f16(acc[mi][ni * 2 + 1], af[mi], bf[ni][2], bf[ni][3]);
                }
        }
    }

    const int rBase = blockIdx.y * TM + wm * 64 + (lane >> 2);
    const int cBase = blockIdx.x * TN + wn * 64 + (lane & 3) * 2;
#pragma unroll
    for (int mi = 0; mi < 4; mi++) {
#pragma unroll
        for (int ni = 0; ni < 8; ni++) {
            int row = rBase + mi * 16;
            int col = cBase + ni * 8;
            *(float2*)(g_Y + (size_t)row * NBIG + col) =
                make_float2(acc[mi][ni][0], acc[mi][ni][1]);
            *(float2*)(g_Y + (size_t)(row + 8) * NBIG + col) =
                make_float2(acc[mi][ni][2], acc[mi][ni][3]);
        }
    }
}

/* ------------------------------------------------------------------ */
/* score_kernel (unchanged, 102 us)                                   */
/* ------------------------------------------------------------------ */
__global__ void __launch_bounds__(320) score_kernel(
    const float* __restrict__ ab1, const float* __restrict__ ab2,
    const float* __restrict__ linW, const float* __restrict__ linb) {
    const int b = blockIdx.x;
    const int tid = threadIdx.x;
    const int lane = tid & 31;
    const int w = tid >> 5;
    const int k = w >> 1;
    const int half = w & 1;
    const float* Yb = g_Y + (size_t)b * C_ * NBIG;
    const int off = k * MID_ + half * 256;

    __shared__ float s_part[10][36];
    __shared__ float s_sc[K_ * 36];
    __shared__ float s_l[36];

    float b1r[8], b2r[8];
#pragma unroll
    for (int it = 0; it < 2; it++) {
        float4 v1 = *(const float4*)(ab1 + off + it * 128 + lane * 4);
        float4 v2 = *(const float4*)(ab2 + off + it * 128 + lane * 4);
        b1r[it*4] = v1.x; b1r[it*4+1] = v1.y; b1r[it*4+2] = v1.z; b1r[it*4+3] = v1.w;
        b2r[it*4] = v2.x; b2r[it*4+1] = v2.y; b2r[it*4+2] = v2.z; b2r[it*4+3] = v2.w;
    }

    float kv[6][8];
#pragma unroll
    for (int d = 0; d < 6; d++) {
        const float* kp = Yb + (size_t)d * NBIG + K_ * MID_ + off;
#pragma unroll
        for (int it = 0; it < 2; it++) {
            float4 v = *(const float4*)(kp + it * 128 + lane * 4);
            kv[d][it*4]   = v.x + b2r[it*4];
            kv[d][it*4+1] = v.y + b2r[it*4+1];
            kv[d][it*4+2] = v.z + b2r[it*4+2];
            kv[d][it*4+3] = v.w + b2r[it*4+3];
        }
    }

#pragma unroll
    for (int c = 0; c < 6; c++) {
        float q[8];
        const float* qp = Yb + (size_t)c * NBIG + off;
#pragma unroll
        for (int it = 0; it < 2; it++) {
            float4 v = *(const float4*)(qp + it * 128 + lane * 4);
            q[it*4]   = v.x + b1r[it*4];
            q[it*4+1] = v.y + b1r[it*4+1];
            q[it*4+2] = v.z + b1r[it*4+2];
            q[it*4+3] = v.w + b1r[it*4+3];
        }
        float acc[6];
#pragma unroll
        for (int d = 0; d < 6; d++) {
            float a = 0.f;
#pragma unroll
            for (int m = 0; m < 8; m++) a += q[m] * kv[d][m];
            acc[d] = a;
        }
#pragma unroll
        for (int o = 16; o; o >>= 1)
#pragma unroll
            for (int d = 0; d < 6; d++) acc[d] += __shfl_xor_sync(0xffffffffu, acc[d], o);
        if (lane == 0)
#pragma unroll
            for (int d = 0; d < 6; d++) s_part[w][c * 6 + d] = acc[d];
    }
    __syncthreads();

    if (tid < 30) {
        int k2 = tid / 6, c = tid - k2 * 6;
        float v[6];
#pragma unroll
        for (int d = 0; d < 6; d++)
            v[d] = s_part[k2 * 2][c * 6 + d] + s_part[k2 * 2 + 1][c * 6 + d];
        float mx = v[0];
#pragma unroll
        for (int d = 1; d < 6; d++) mx = fmaxf(mx, v[d]);
        float e[6], sum = 0.f;
#pragma unroll
        for (int d = 0; d < 6; d++) { e[d] = expf(v[d] - mx); sum += e[d]; }
        float inv = 1.f / sum;
#pragma unroll
        for (int d = 0; d < 6; d++) s_sc[k2 * 36 + c * 6 + d] = e[d] * inv;
    }
    __syncthreads();

    if (tid < 36) {
        int c = tid / 6, e = tid - (tid / 6) * 6;
        float acc = linb[e];
#pragma unroll
        for (int k2 = 0; k2 < K_; k2++)
#pragma unroll
            for (int d = 0; d < 6; d++)
                acc += s_sc[k2 * 36 + c * 6 + d] * linW[(k2 * 6 + d) * 6 + e];
        s_l[tid] = acc;
    }
    __syncthreads();

    if (tid < 6) {
        float* r = s_l + tid * 6;
        float mx = r[0];
#pragma unroll
        for (int e = 1; e < 6; e++) mx = fmaxf(mx, r[e]);
        float ev[6], sum = 0.f;
#pragma unroll
        for (int e = 0; e < 6; e++) { ev[e] = expf(r[e] - mx); sum += ev[e]; }
        float inv = 1.f / sum;
        float* ap = g_A + (size_t)b * 36 + tid * 6;
#pragma unroll
        for (int e = 0; e < 6; e++) ap[e] = ev[e] * inv;
    }
}

/* ------------------------------------------------------------------ */
/* hg_fused: g_HG = h @ gW2 with h = BN1(PReLU(A@xg + gb1)) computed  */
/* inline at A-tile load. 256 threads, full reg budget (no min-blocks)*/
/* ------------------------------------------------------------------ */
#define SBM 128
#define SBN 128
#define SBK 16
__global__ void __launch_bounds__(256) hg_fused_kernel(
    const float* __restrict__ gW2, const float* __restrict__ gb1,
    const float* __restrict__ prelu_a,
    const float* __restrict__ bn1g, const float* __restrict__ bn1b,
    const float* __restrict__ bn1m, const float* __restrict__ bn1v) {
    __shared__ float As[SBK][SBM];
    __shared__ float Bs[SBK][SBN];
    __shared__ float rowp[SBM][9];   /* a0..a5, scale, mu, beta */

    const int bx = blockIdx.x;       /* 0..1 */
    const int by = blockIdx.y;       /* 0..191 */
    const int tid = threadIdx.x;
    const float pa = prelu_a[0];

    if (tid < SBM) {
        int r = by * SBM + tid;
        int b = r / 6, c = r - b * 6;
        const float* ap = g_A + (size_t)b * 36 + c * 6;
#pragma unroll
        for (int d = 0; d < 6; d++) rowp[tid][d] = ap[d];
        rowp[tid][6] = bn1g[c] * (1.f / sqrtf(bn1v[c] + 1e-5f));
        rowp[tid][7] = bn1m[c];
        rowp[tid][8] = bn1b[c];
    }
    __syncthreads();

    const int tx = tid & 15;
    const int ty = tid >> 4;
    const int a_row = tid >> 2;          /* 0..63 */
    const int a_col = (tid & 3) << 2;    /* 0,4,8,12 */
    const int b_row = tid >> 5;          /* 0..7 */
    const int b_col = (tid & 31) << 2;
    const float* Bb = gW2 + bx * SBN;

    float acc[8][8];
#pragma unroll
    for (int i = 0; i < 8; i++)
#pragma unroll
        for (int j = 0; j < 8; j++) acc[i][j] = 0.f;

    for (int k0 = 0; k0 < HID_; k0 += SBK) {
        /* A-tile with inline h computation: 2 rows per thread */
#pragma unroll
        for (int i = 0; i < 2; i++) {
            int r = a_row + i * 64;
            int gr = by * SBM + r;
            size_t xgb = ((size_t)(gr / 6)) * 6 * NBIG + 2 * K_ * MID_ + k0 + a_col;
            float4 z = *(const float4*)(gb1 + k0 + a_col);
            const float* rp = rowp[r];
#pragma unroll
            for (int d = 0; d < 6; d++) {
                float4 v = *(const float4*)(g_Y + xgb + (size_t)d * NBIG);
                float ad = rp[d];
                z.x += ad * v.x; z.y += ad * v.y; z.z += ad * v.z; z.w += ad * v.w;
            }
            z.x = z.x >= 0.f ? z.x : pa * z.x;
            z.y = z.y >= 0.f ? z.y : pa * z.y;
            z.z = z.z >= 0.f ? z.z : pa * z.z;
            z.w = z.w >= 0.f ? z.w : pa * z.w;
            float sc = rp[6], mu = rp[7], be = rp[8];
            As[a_col + 0][r] = (z.x - mu) * sc + be;
            As[a_col + 1][r] = (z.y - mu) * sc + be;
            As[a_col + 2][r] = (z.z - mu) * sc + be;
            As[a_col + 3][r] = (z.w - mu) * sc + be;
        }
        /* B-tile */
#pragma unroll
        for (int i = 0; i < 2; i++) {
            int r = b_row + i * 8;
            *(float4*)&Bs[r][b_col] =
                *(const float4*)(Bb + (size_t)(k0 + r) * OUT_ + b_col);
        }
        __syncthreads();
#pragma unroll
        for (int kk = 0; kk < SBK; kk++) {
            float4 a0 = *(const float4*)&As[kk][ty * 8];
            float4 a1 = *(const float4*)&As[kk][ty * 8 + 4];
            float4 b0 = *(const float4*)&Bs[kk][tx * 8];
            float4 b1 = *(const float4*)&Bs[kk][tx * 8 + 4];
            float ar[8] = {a0.x, a0.y, a0.z, a0.w, a1.x, a1.y, a1.z, a1.w};
            float br[8] = {b0.x, b0.y, b0.z, b0.w, b1.x, b1.y, b1.z, b1.w};
#pragma unroll
            for (int i = 0; i < 8; i++)
#pragma unroll
                for (int j = 0; j < 8; j++) acc[i][j] += ar[i] * br[j];
        }
        __syncthreads();
    }
    float* Cp = g_HG + (size_t)(by * SBM + ty * 8) * OUT_ + bx * SBN + tx * 8;
#pragma unroll
    for (int i = 0; i < 8; i++)
#pragma unroll
        for (int j = 0; j < 8; j += 4)
            *(float4*)(Cp + (size_t)i * OUT_ + j) =
                make_float4(acc[i][j], acc[i][j+1], acc[i][j+2], acc[i][j+3]);
}

/* ------------------------------------------------------------------ */
__global__ void __launch_bounds__(256) out_kernel(
    const float* __restrict__ gb2,
    const float* __restrict__ bn2g, const float* __restrict__ bn2b,
    const float* __restrict__ bn2m, const float* __restrict__ bn2v,
    float* __restrict__ out) {
    const int b = blockIdx.x;
    const int o = threadIdx.x;
    __shared__ float sA[36];
    if (o < 36) sA[o] = g_A[(size_t)b * 36 + o];
    __syncthreads();
    float hgv[6];
#pragma unroll
    for (int d = 0; d < 6; d++)
        hgv[d] = g_HG[((size_t)b * 6 + d) * OUT_ + o];
    float g2 = gb2[o];
#pragma unroll
    for (int c = 0; c < 6; c++) {
        float acc = g2;
#pragma unroll
        for (int d = 0; d < 6; d++) acc += sA[c * 6 + d] * hgv[d];
        float inv = bn2g[c] * (1.f / sqrtf(bn2v[c] + 1e-5f));
        acc = (acc - bn2m[c]) * inv + bn2b[c];
        out[((size_t)b * C_ + c) * OUT_ + o] = acc;
    }
}

/* ------------------------------------------------------------------ */
extern "C" void kernel_launch(void* const* d_in, const int* in_sizes, int n_in,
                              void* d_out, int out_size) {
    const float* x       = (const float*)d_in[0];
    const float* aW1     = (const float*)d_in[1];
    const float* ab1     = (const float*)d_in[2];
    const float* aW2     = (const float*)d_in[3];
    const float* ab2     = (const float*)d_in[4];
    const float* linW    = (const float*)d_in[5];
    const float* linb    = (const float*)d_in[6];
    const float* gW1     = (const float*)d_in[7];
    const float* gb1     = (const float*)d_in[8];
    const float* gW2     = (const float*)d_in[9];
    const float* gb2     = (const float*)d_in[10];
    const float* prelu_a = (const float*)d_in[11];
    const float* bn1g    = (const float*)d_in[12];
    const float* bn1b    = (const float*)d_in[13];
    const float* bn1m    = (const float*)d_in[14];
    const float* bn1v    = (const float*)d_in[15];
    const float* bn2g    = (const float*)d_in[16];
    const float* bn2b    = (const float*)d_in[17];
    const float* bn2m    = (const float*)d_in[18];
    const float* bn2v    = (const float*)d_in[19];
    float* out = (float*)d_out;

    static bool attr_set = false;
    if (!attr_set) {
        cudaFuncSetAttribute(gemm_kernel,
                             cudaFuncAttributeMaxDynamicSharedMemorySize, SMEM_TOTAL);
        attr_set = true;
    }

    packA_kernel<<<(MROWS / 16) * KCDD * 32 / 256, 256>>>(x);
    packB_kernel<<<(NBIG / 16) * KCDD * 32 / 256, 256>>>(aW1, aW2, gW1);

    dim3 grid(NBIG / TN, MROWS / TM);   /* 22 x 192 */
    gemm_kernel<<<grid, 256, SMEM_TOTAL>>>();

    score_kernel<<<B_, 320>>>(ab1, ab2, linW, linb);
    {
        dim3 g2(OUT_ / SBN, MROWS / SBM);   /* 2 x 192 */
        hg_fused_kernel<<<g2, 256>>>(gW2, gb1, prelu_a, bn1g, bn1b, bn1m, bn1v);
    }
    out_kernel<<<B_, OUT_>>>(gb2, bn2g, bn2b, bn2m, bn2v, out);
}

// round 13
// speedup vs baseline: 1.0443x; 1.0443x over previous
#include <cuda_runtime.h>
#include <cuda_fp16.h>
#include <math.h>
#include <stdint.h>

#define B_    4096
#define C_    6
#define L_    1024
#define MID_  512
#define HID_  512
#define OUT_  256
#define K_    5
#define NBIG  5632
#define MROWS (B_ * C_)
#define KCDD  128              /* dedup k-chunks: hi [0,64) + lo [64,128) */

#define TM 128
#define TN 256
#define NSTG 48
#define ASTG_BYTES 16384
#define STG_BYTES  49152
#define SMEM_TOTAL (4 * STG_BYTES)

__device__ uint4 g_Ah[(size_t)(MROWS / 16) * KCDD * 32];   /* 100 MB */
__device__ uint4 g_Bh[(size_t)(NBIG / 16) * KCDD * 32];    /*  23 MB */
__device__ float g_Y[(size_t)MROWS * NBIG];
__device__ float g_A[(size_t)B_ * 36];
__device__ float g_H[(size_t)MROWS * HID_];
__device__ float g_HG[(size_t)MROWS * OUT_];

__device__ __forceinline__ uint32_t smem_u32(const void* p) {
    uint32_t a;
    asm("{ .reg .u64 t; cvta.to.shared.u64 t, %1; cvt.u32.u64 %0, t; }" : "=r"(a) : "l"(p));
    return a;
}
__device__ __forceinline__ void cpa16(uint32_t s, const void* g) {
    asm volatile("cp.async.cg.shared.global [%0], [%1], 16;" :: "r"(s), "l"(g) : "memory");
}
__device__ __forceinline__ void lds128(uint32_t* r, uint32_t a) {
    asm volatile("ld.shared.v4.b32 {%0,%1,%2,%3}, [%4];"
                 : "=r"(r[0]), "=r"(r[1]), "=r"(r[2]), "=r"(r[3]) : "r"(a));
}
__device__ __forceinline__ void mma_f16(float* c, const uint32_t* a, uint32_t b0, uint32_t b1) {
    asm volatile(
        "mma.sync.aligned.m16n8k16.row.col.f32.f16.f16.f32 "
        "{%0,%1,%2,%3}, {%4,%5,%6,%7}, {%8,%9}, {%0,%1,%2,%3};"
        : "+f"(c[0]), "+f"(c[1]), "+f"(c[2]), "+f"(c[3])
        : "r"(a[0]), "r"(a[1]), "r"(a[2]), "r"(a[3]), "r"(b0), "r"(b1));
}
__device__ __forceinline__ __half cvt_split(float x, bool lo) {
    __half hi = __float2half_rn(x);
    if (!lo) return hi;
    return __float2half_rn(x - __half2float(hi));
}
/* streaming (evict-first) helpers — semantics identical, cache policy only */
__device__ __forceinline__ float4 ldcs4(const float* p) {
    return __ldcs((const float4*)p);
}
__device__ __forceinline__ void stcs2(float* p, float2 v) {
    __stcs((float2*)p, v);
}

/* ------------------------- packs (dedup) -------------------------- */
__global__ void packA_kernel(const float* __restrict__ X) {
    int cid = blockIdx.x * 256 + threadIdx.x;
    int ln = cid & 31;
    int b = cid >> 5;
    int kc = b & (KCDD - 1);
    int mt = b >> 7;
    bool lo = kc >= 64;
    int l0 = (kc & 63) * 16 + (ln & 3) * 2;
    int r0 = mt * 16 + (ln >> 2);
    float2 x00 = *(const float2*)(X + (size_t)r0 * L_ + l0);
    float2 x10 = *(const float2*)(X + (size_t)(r0 + 8) * L_ + l0);
    float2 x01 = *(const float2*)(X + (size_t)r0 * L_ + l0 + 8);
    float2 x11 = *(const float2*)(X + (size_t)(r0 + 8) * L_ + l0 + 8);
    __half h[8];
    h[0] = cvt_split(x00.x, lo); h[1] = cvt_split(x00.y, lo);
    h[2] = cvt_split(x10.x, lo); h[3] = cvt_split(x10.y, lo);
    h[4] = cvt_split(x01.x, lo); h[5] = cvt_split(x01.y, lo);
    h[6] = cvt_split(x11.x, lo); h[7] = cvt_split(x11.y, lo);
    g_Ah[cid] = *(uint4*)h;
}
__device__ __forceinline__ float fetchW(const float* aW1, const float* aW2,
                                        const float* gW1, int l, int n) {
    if (n < K_ * MID_) {
        return aW1[((size_t)(n >> 9) * L_ + l) * MID_ + (n & 511)];
    } else if (n < 2 * K_ * MID_) {
        int nn = n - K_ * MID_;
        return aW2[((size_t)(nn >> 9) * L_ + l) * MID_ + (nn & 511)];
    }
    return gW1[(size_t)l * HID_ + (n - 2 * K_ * MID_)];
}
__global__ void packB_kernel(const float* __restrict__ aW1,
                             const float* __restrict__ aW2,
                             const float* __restrict__ gW1) {
    int cid = blockIdx.x * 256 + threadIdx.x;
    int ln = cid & 31;
    int b = cid >> 5;
    int kc = b & (KCDD - 1);
    int nt = b >> 7;
    bool lo = kc >= 64;
    int l0 = (kc & 63) * 16 + (ln & 3) * 2;
    int n0 = nt * 16 + (ln >> 2);
    int n1 = n0 + 8;
    __half h[8];
    h[0] = cvt_split(fetchW(aW1, aW2, gW1, l0,     n0), lo);
    h[1] = cvt_split(fetchW(aW1, aW2, gW1, l0 + 1, n0), lo);
    h[2] = cvt_split(fetchW(aW1, aW2, gW1, l0 + 8, n0), lo);
    h[3] = cvt_split(fetchW(aW1, aW2, gW1, l0 + 9, n0), lo);
    h[4] = cvt_split(fetchW(aW1, aW2, gW1, l0,     n1), lo);
    h[5] = cvt_split(fetchW(aW1, aW2, gW1, l0 + 1, n1), lo);
    h[6] = cvt_split(fetchW(aW1, aW2, gW1, l0 + 8, n1), lo);
    h[7] = cvt_split(fetchW(aW1, aW2, gW1, l0 + 9, n1), lo);
    g_Bh[cid] = *(uint4*)h;
}

/* ------------------ big GEMM (dedup stage remap) ------------------ */
struct IssueCtx { uint32_t sb; int mtB, ntB, tid; };

__device__ __forceinline__ void issue_stage(const IssueCtx& cx, int s) {
    uint32_t stBase = cx.sb + (s & 3) * STG_BYTES;
    int akc0 = (s < 16) ? s * 4 : (s < 32) ? 64 + (s - 16) * 4 : (s - 32) * 4;
    int bkc0 = (s < 16) ? s * 4 : (s < 32) ? (s - 16) * 4 : 64 + (s - 32) * 4;
#pragma unroll
    for (int i = 0; i < 4; i++) {
        int cid = cx.tid + i * 256;
        int ln = cid & 31, bb = cid >> 5;
        int kci = bb >> 3, mti = bb & 7;
        uint32_t sa = stBase + (uint32_t)(((kci * 8 + mti) * 32 + ln) * 16);
        const uint4* ga = g_Ah + ((size_t)(cx.mtB + mti) * KCDD + akc0 + kci) * 32 + ln;
        cpa16(sa, ga);
    }
#pragma unroll
    for (int i = 0; i < 8; i++) {
        int cid = cx.tid + i * 256;
        int ln = cid & 31, bb = cid >> 5;
        int kci = bb >> 4, nti = bb & 15;
        uint32_t sb2 = stBase + ASTG_BYTES + (uint32_t)(((kci * 16 + nti) * 32 + ln) * 16);
        const uint4* gb = g_Bh + ((size_t)(cx.ntB + nti) * KCDD + bkc0 + kci) * 32 + ln;
        cpa16(sb2, gb);
    }
    asm volatile("cp.async.commit_group;" ::: "memory");
}

__global__ void __launch_bounds__(256, 1) gemm_kernel() {
    extern __shared__ char smem[];
    const uint32_t sb = smem_u32(smem);
    const int tid = threadIdx.x;
    const int lane = tid & 31;
    const int wid = tid >> 5;
    const int wm = wid & 1;
    const int wn = wid >> 1;
    const int mtB = blockIdx.y * 8;
    const int ntB = blockIdx.x * 16;

    IssueCtx cx{sb, mtB, ntB, tid};

    float acc[4][8][4];
#pragma unroll
    for (int a = 0; a < 4; a++)
#pragma unroll
        for (int bq = 0; bq < 8; bq++)
#pragma unroll
            for (int c = 0; c < 4; c++) acc[a][bq][c] = 0.f;

    issue_stage(cx, 0);
    issue_stage(cx, 1);
    issue_stage(cx, 2);

    for (int s = 0; s < NSTG; s++) {
        asm volatile("cp.async.wait_group 2;" ::: "memory");
        __syncthreads();
        if (s + 3 < NSTG) issue_stage(cx, s + 3);
        else asm volatile("cp.async.commit_group;" ::: "memory");

        uint32_t stBase = sb + (s & 3) * STG_BYTES;
#pragma unroll
        for (int kc = 0; kc < 4; kc++) {
            uint32_t af[4][4], bf[4][4];
#pragma unroll
            for (int mi = 0; mi < 4; mi++)
                lds128(af[mi], stBase + (uint32_t)((((kc * 8) + wm * 4 + mi) * 32 + lane) * 16));
#pragma unroll
            for (int ni = 0; ni < 4; ni++)
                lds128(bf[ni], stBase + ASTG_BYTES +
                               (uint32_t)((((kc * 16) + wn * 4 + ni) * 32 + lane) * 16));
#pragma unroll
            for (int mi = 0; mi < 4; mi++)
#pragma unroll
                for (int ni = 0; ni < 4; ni++) {
                    mma_f16(acc[mi][ni * 2],     af[mi], bf[ni][0], bf[ni][1]);
                    mma_f16(acc[mi][ni * 2 + 1], af[mi], bf[ni][2], bf[ni][3]);
                }
        }
    }

    /* epilogue: streaming stores (evict-first) — keep B resident in L2 */
    const int rBase = blockIdx.y * TM + wm * 64 + (lane >> 2);
    const int cBase = blockIdx.x * TN + wn * 64 + (lane & 3) * 2;
#pragma unroll
    for (int mi = 0; mi < 4; mi++) {
#pragma unroll
        for (int ni = 0; ni < 8; ni++) {
            int row = rBase + mi * 16;
            int col = cBase + ni * 8;
            stcs2(g_Y + (size_t)row * NBIG + col,
                  make_float2(acc[mi][ni][0], acc[mi][ni][1]));
            stcs2(g_Y + (size_t)(row + 8) * NBIG + col,
                  make_float2(acc[mi][ni][2], acc[mi][ni][3]));
        }
    }
}

/* ------------------------------------------------------------------ */
/* score_kernel (round-9 + __ldcs on single-use q/kv streams)         */
/* ------------------------------------------------------------------ */
__global__ void __launch_bounds__(320) score_kernel(
    const float* __restrict__ ab1, const float* __restrict__ ab2,
    const float* __restrict__ linW, const float* __restrict__ linb) {
    const int b = blockIdx.x;
    const int tid = threadIdx.x;
    const int lane = tid & 31;
    const int w = tid >> 5;
    const int k = w >> 1;
    const int half = w & 1;
    const float* Yb = g_Y + (size_t)b * C_ * NBIG;
    const int off = k * MID_ + half * 256;

    __shared__ float s_part[10][36];
    __shared__ float s_sc[K_ * 36];
    __shared__ float s_l[36];

    float b1r[8], b2r[8];
#pragma unroll
    for (int it = 0; it < 2; it++) {
        float4 v1 = *(const float4*)(ab1 + off + it * 128 + lane * 4);
        float4 v2 = *(const float4*)(ab2 + off + it * 128 + lane * 4);
        b1r[it*4] = v1.x; b1r[it*4+1] = v1.y; b1r[it*4+2] = v1.z; b1r[it*4+3] = v1.w;
        b2r[it*4] = v2.x; b2r[it*4+1] = v2.y; b2r[it*4+2] = v2.z; b2r[it*4+3] = v2.w;
    }

    float kv[6][8];
#pragma unroll
    for (int d = 0; d < 6; d++) {
        const float* kp = Yb + (size_t)d * NBIG + K_ * MID_ + off;
#pragma unroll
        for (int it = 0; it < 2; it++) {
            float4 v = ldcs4(kp + it * 128 + lane * 4);
            kv[d][it*4]   = v.x + b2r[it*4];
            kv[d][it*4+1] = v.y + b2r[it*4+1];
            kv[d][it*4+2] = v.z + b2r[it*4+2];
            kv[d][it*4+3] = v.w + b2r[it*4+3];
        }
    }

#pragma unroll
    for (int c = 0; c < 6; c++) {
        float q[8];
        const float* qp = Yb + (size_t)c * NBIG + off;
#pragma unroll
        for (int it = 0; it < 2; it++) {
            float4 v = ldcs4(qp + it * 128 + lane * 4);
            q[it*4]   = v.x + b1r[it*4];
            q[it*4+1] = v.y + b1r[it*4+1];
            q[it*4+2] = v.z + b1r[it*4+2];
            q[it*4+3] = v.w + b1r[it*4+3];
        }
        float acc[6];
#pragma unroll
        for (int d = 0; d < 6; d++) {
            float a = 0.f;
#pragma unroll
            for (int m = 0; m < 8; m++) a += q[m] * kv[d][m];
            acc[d] = a;
        }
#pragma unroll
        for (int o = 16; o; o >>= 1)
#pragma unroll
            for (int d = 0; d < 6; d++) acc[d] += __shfl_xor_sync(0xffffffffu, acc[d], o);
        if (lane == 0)
#pragma unroll
            for (int d = 0; d < 6; d++) s_part[w][c * 6 + d] = acc[d];
    }
    __syncthreads();

    if (tid < 30) {
        int k2 = tid / 6, c = tid - k2 * 6;
        float v[6];
#pragma unroll
        for (int d = 0; d < 6; d++)
            v[d] = s_part[k2 * 2][c * 6 + d] + s_part[k2 * 2 + 1][c * 6 + d];
        float mx = v[0];
#pragma unroll
        for (int d = 1; d < 6; d++) mx = fmaxf(mx, v[d]);
        float e[6], sum = 0.f;
#pragma unroll
        for (int d = 0; d < 6; d++) { e[d] = expf(v[d] - mx); sum += e[d]; }
        float inv = 1.f / sum;
#pragma unroll
        for (int d = 0; d < 6; d++) s_sc[k2 * 36 + c * 6 + d] = e[d] * inv;
    }
    __syncthreads();

    if (tid < 36) {
        int c = tid / 6, e = tid - (tid / 6) * 6;
        float acc = linb[e];
#pragma unroll
        for (int k2 = 0; k2 < K_; k2++)
#pragma unroll
            for (int d = 0; d < 6; d++)
                acc += s_sc[k2 * 36 + c * 6 + d] * linW[(k2 * 6 + d) * 6 + e];
        s_l[tid] = acc;
    }
    __syncthreads();

    if (tid < 6) {
        float* r = s_l + tid * 6;
        float mx = r[0];
#pragma unroll
        for (int e = 1; e < 6; e++) mx = fmaxf(mx, r[e]);
        float ev[6], sum = 0.f;
#pragma unroll
        for (int e = 0; e < 6; e++) { ev[e] = expf(r[e] - mx); sum += ev[e]; }
        float inv = 1.f / sum;
        float* ap = g_A + (size_t)b * 36 + tid * 6;
#pragma unroll
        for (int e = 0; e < 6; e++) ap[e] = ev[e] * inv;
    }
}

/* ------------------------------------------------------------------ */
/* h_kernel (round-9 + __ldcs on xg)                                  */
/* ------------------------------------------------------------------ */
__global__ void __launch_bounds__(256) h_kernel(
    const float* __restrict__ gb1, const float* __restrict__ prelu_a,
    const float* __restrict__ bn1g, const float* __restrict__ bn1b,
    const float* __restrict__ bn1m, const float* __restrict__ bn1v) {
    int idx = blockIdx.x * 256 + threadIdx.x;
    int j4 = idx & 127;
    int r = idx >> 7;
    int b = r / 6;
    int c = r - b * 6;
    const float* Ab = g_A + (size_t)b * 36 + c * 6;
    float a0 = Ab[0], a1 = Ab[1], a2 = Ab[2], a3 = Ab[3], a4 = Ab[4], a5 = Ab[5];
    const float* xg = g_Y + (size_t)b * 6 * NBIG + 2 * K_ * MID_ + j4 * 4;
    float4 z = *(const float4*)(gb1 + j4 * 4);
    float4 v;
#define ACC4(aa, d) \
    v = ldcs4(xg + (size_t)(d) * NBIG); \
    z.x += (aa) * v.x; z.y += (aa) * v.y; z.z += (aa) * v.z; z.w += (aa) * v.w;
    ACC4(a0, 0) ACC4(a1, 1) ACC4(a2, 2) ACC4(a3, 3) ACC4(a4, 4) ACC4(a5, 5)
#undef ACC4
    float pa = prelu_a[0];
    z.x = z.x >= 0.f ? z.x : pa * z.x;
    z.y = z.y >= 0.f ? z.y : pa * z.y;
    z.z = z.z >= 0.f ? z.z : pa * z.z;
    z.w = z.w >= 0.f ? z.w : pa * z.w;
    float inv = bn1g[c] * (1.f / sqrtf(bn1v[c] + 1e-5f));
    float mu = bn1m[c], bb = bn1b[c];
    z.x = (z.x - mu) * inv + bb;
    z.y = (z.y - mu) * inv + bb;
    z.z = (z.z - mu) * inv + bb;
    z.w = (z.w - mu) * inv + bb;
    *(float4*)(g_H + (size_t)r * HID_ + j4 * 4) = z;
}

/* ------------------------------------------------------------------ */
#define SBM 128
#define SBN 128
#define SBK 16
__global__ void __launch_bounds__(256, 2) hg_gemm_kernel(const float* __restrict__ gW2) {
    __shared__ float As[SBK][SBM];
    __shared__ float Bs[SBK][SBN];
    const int bx = blockIdx.x;
    const int by = blockIdx.y;
    const int tid = threadIdx.x;
    const int tx = tid & 15;
    const int ty = tid >> 4;
    const int a_row = tid >> 2;
    const int a_col = (tid & 3) << 2;
    const int b_row = tid >> 5;
    const int b_col = (tid & 31) << 2;
    const float* Ab = g_H + (size_t)(by * SBM) * HID_;
    const float* Bb = gW2 + bx * SBN;

    float acc[8][8];
#pragma unroll
    for (int i = 0; i < 8; i++)
#pragma unroll
        for (int j = 0; j < 8; j++) acc[i][j] = 0.f;

    for (int k0 = 0; k0 < HID_; k0 += SBK) {
#pragma unroll
        for (int i = 0; i < 2; i++) {
            int r = a_row + i * 64;
            float4 v = *(const float4*)(Ab + (size_t)r * HID_ + k0 + a_col);
            As[a_col + 0][r] = v.x;
            As[a_col + 1][r] = v.y;
            As[a_col + 2][r] = v.z;
            As[a_col + 3][r] = v.w;
        }
#pragma unroll
        for (int i = 0; i < 2; i++) {
            int r = b_row + i * 8;
            *(float4*)&Bs[r][b_col] =
                *(const float4*)(Bb + (size_t)(k0 + r) * OUT_ + b_col);
        }
        __syncthreads();
#pragma unroll
        for (int kk = 0; kk < SBK; kk++) {
            float4 a0 = *(const float4*)&As[kk][ty * 8];
            float4 a1 = *(const float4*)&As[kk][ty * 8 + 4];
            float4 b0 = *(const float4*)&Bs[kk][tx * 8];
            float4 b1 = *(const float4*)&Bs[kk][tx * 8 + 4];
            float ar[8] = {a0.x, a0.y, a0.z, a0.w, a1.x, a1.y, a1.z, a1.w};
            float br[8] = {b0.x, b0.y, b0.z, b0.w, b1.x, b1.y, b1.z, b1.w};
#pragma unroll
            for (int i = 0; i < 8; i++)
#pragma unroll
                for (int j = 0; j < 8; j++) acc[i][j] += ar[i] * br[j];
        }
        __syncthreads();
    }
    float* Cp = g_HG + (size_t)(by * SBM + ty * 8) * OUT_ + bx * SBN + tx * 8;
#pragma unroll
    for (int i = 0; i < 8; i++)
#pragma unroll
        for (int j = 0; j < 8; j += 4)
            *(float4*)(Cp + (size_t)i * OUT_ + j) =
                make_float4(acc[i][j], acc[i][j+1], acc[i][j+2], acc[i][j+3]);
}

/* ------------------------------------------------------------------ */
__global__ void __launch_bounds__(256) out_kernel(
    const float* __restrict__ gb2,
    const float* __restrict__ bn2g, const float* __restrict__ bn2b,
    const float* __restrict__ bn2m, const float* __restrict__ bn2v,
    float* __restrict__ out) {
    const int b = blockIdx.x;
    const int o = threadIdx.x;
    __shared__ float sA[36];
    if (o < 36) sA[o] = g_A[(size_t)b * 36 + o];
    __syncthreads();
    float hgv[6];
#pragma unroll
    for (int d = 0; d < 6; d++)
        hgv[d] = __ldcs(&g_HG[((size_t)b * 6 + d) * OUT_ + o]);
    float g2 = gb2[o];
#pragma unroll
    for (int c = 0; c < 6; c++) {
        float acc = g2;
#pragma unroll
        for (int d = 0; d < 6; d++) acc += sA[c * 6 + d] * hgv[d];
        float inv = bn2g[c] * (1.f / sqrtf(bn2v[c] + 1e-5f));
        acc = (acc - bn2m[c]) * inv + bn2b[c];
        out[((size_t)b * C_ + c) * OUT_ + o] = acc;
    }
}

/* ------------------------------------------------------------------ */
extern "C" void kernel_launch(void* const* d_in, const int* in_sizes, int n_in,
                              void* d_out, int out_size) {
    const float* x       = (const float*)d_in[0];
    const float* aW1     = (const float*)d_in[1];
    const float* ab1     = (const float*)d_in[2];
    const float* aW2     = (const float*)d_in[3];
    const float* ab2     = (const float*)d_in[4];
    const float* linW    = (const float*)d_in[5];
    const float* linb    = (const float*)d_in[6];
    const float* gW1     = (const float*)d_in[7];
    const float* gb1     = (const float*)d_in[8];
    const float* gW2     = (const float*)d_in[9];
    const float* gb2     = (const float*)d_in[10];
    const float* prelu_a = (const float*)d_in[11];
    const float* bn1g    = (const float*)d_in[12];
    const float* bn1b    = (const float*)d_in[13];
    const float* bn1m    = (const float*)d_in[14];
    const float* bn1v    = (const float*)d_in[15];
    const float* bn2g    = (const float*)d_in[16];
    const float* bn2b    = (const float*)d_in[17];
    const float* bn2m    = (const float*)d_in[18];
    const float* bn2v    = (const float*)d_in[19];
    float* out = (float*)d_out;

    static bool attr_set = false;
    if (!attr_set) {
        cudaFuncSetAttribute(gemm_kernel,
                             cudaFuncAttributeMaxDynamicSharedMemorySize, SMEM_TOTAL);
        attr_set = true;
    }

    packA_kernel<<<(MROWS / 16) * KCDD * 32 / 256, 256>>>(x);
    packB_kernel<<<(NBIG / 16) * KCDD * 32 / 256, 256>>>(aW1, aW2, gW1);

    dim3 grid(NBIG / TN, MROWS / TM);   /* 22 x 192 */
    gemm_kernel<<<grid, 256, SMEM_TOTAL>>>();

    score_kernel<<<B_, 320>>>(ab1, ab2, linW, linb);
    h_kernel<<<MROWS * (HID_ / 4) / 256, 256>>>(gb1, prelu_a, bn1g, bn1b, bn1m, bn1v);
    {
        dim3 g2(OUT_ / SBN, MROWS / SBM);
        hg_gemm_kernel<<<g2, 256>>>(gW2);
    }
    out_kernel<<<B_, OUT_>>>(gb2, bn2g, bn2b, bn2m, bn2v, out);
}

// round 15
// speedup vs baseline: 1.0485x; 1.0040x over previous
#include <cuda_runtime.h>
#include <cuda_fp16.h>
#include <math.h>
#include <stdint.h>

#define B_    4096
#define C_    6
#define L_    1024
#define MID_  512
#define HID_  512
#define OUT_  256
#define K_    5
#define NBIG  5632
#define MROWS (B_ * C_)
#define KCDD  128              /* dedup k-chunks: hi [0,64) + lo [64,128) */

#define TM 128
#define TN 256
#define NSTG2 32               /* 16 fused (Ahi+Alo)xBhi + 16 AhixBlo */
#define STG2  65536            /* A0 16K @0, A1 16K @16K, B 32K @32K */
#define SMEM_TOTAL2 (3 * STG2) /* 196608 */

__device__ uint4 g_Ah[(size_t)(MROWS / 16) * KCDD * 32];   /* 100 MB */
__device__ uint4 g_Bh[(size_t)(NBIG / 16) * KCDD * 32];    /*  23 MB */
__device__ float g_Y[(size_t)MROWS * NBIG];
__device__ float g_A[(size_t)B_ * 36];
__device__ float g_H[(size_t)MROWS * HID_];
__device__ float g_HG[(size_t)MROWS * OUT_];

__device__ __forceinline__ uint32_t smem_u32(const void* p) {
    uint32_t a;
    asm("{ .reg .u64 t; cvta.to.shared.u64 t, %1; cvt.u32.u64 %0, t; }" : "=r"(a) : "l"(p));
    return a;
}
__device__ __forceinline__ void cpa16(uint32_t s, const void* g) {
    asm volatile("cp.async.cg.shared.global [%0], [%1], 16;" :: "r"(s), "l"(g) : "memory");
}
__device__ __forceinline__ void lds128(uint32_t* r, uint32_t a) {
    asm volatile("ld.shared.v4.b32 {%0,%1,%2,%3}, [%4];"
                 : "=r"(r[0]), "=r"(r[1]), "=r"(r[2]), "=r"(r[3]) : "r"(a));
}
__device__ __forceinline__ void mma_f16(float* c, const uint32_t* a, uint32_t b0, uint32_t b1) {
    asm volatile(
        "mma.sync.aligned.m16n8k16.row.col.f32.f16.f16.f32 "
        "{%0,%1,%2,%3}, {%4,%5,%6,%7}, {%8,%9}, {%0,%1,%2,%3};"
        : "+f"(c[0]), "+f"(c[1]), "+f"(c[2]), "+f"(c[3])
        : "r"(a[0]), "r"(a[1]), "r"(a[2]), "r"(a[3]), "r"(b0), "r"(b1));
}
__device__ __forceinline__ __half cvt_split(float x, bool lo) {
    __half hi = __float2half_rn(x);
    if (!lo) return hi;
    return __float2half_rn(x - __half2float(hi));
}
/* streaming (evict-first) helpers — semantics identical, cache policy only */
__device__ __forceinline__ float4 ldcs4(const float* p) {
    return __ldcs((const float4*)p);
}
__device__ __forceinline__ void stcs2(float* p, float2 v) {
    __stcs((float2*)p, v);
}

/* ------------------------- packs (dedup) -------------------------- */
__global__ void packA_kernel(const float* __restrict__ X) {
    int cid = blockIdx.x * 256 + threadIdx.x;
    int ln = cid & 31;
    int b = cid >> 5;
    int kc = b & (KCDD - 1);
    int mt = b >> 7;
    bool lo = kc >= 64;
    int l0 = (kc & 63) * 16 + (ln & 3) * 2;
    int r0 = mt * 16 + (ln >> 2);
    float2 x00 = *(const float2*)(X + (size_t)r0 * L_ + l0);
    float2 x10 = *(const float2*)(X + (size_t)(r0 + 8) * L_ + l0);
    float2 x01 = *(const float2*)(X + (size_t)r0 * L_ + l0 + 8);
    float2 x11 = *(const float2*)(X + (size_t)(r0 + 8) * L_ + l0 + 8);
    __half h[8];
    h[0] = cvt_split(x00.x, lo); h[1] = cvt_split(x00.y, lo);
    h[2] = cvt_split(x10.x, lo); h[3] = cvt_split(x10.y, lo);
    h[4] = cvt_split(x01.x, lo); h[5] = cvt_split(x01.y, lo);
    h[6] = cvt_split(x11.x, lo); h[7] = cvt_split(x11.y, lo);
    g_Ah[cid] = *(uint4*)h;
}
__device__ __forceinline__ float fetchW(const float* aW1, const float* aW2,
                                        const float* gW1, int l, int n) {
    if (n < K_ * MID_) {
        return aW1[((size_t)(n >> 9) * L_ + l) * MID_ + (n & 511)];
    } else if (n < 2 * K_ * MID_) {
        int nn = n - K_ * MID_;
        return aW2[((size_t)(nn >> 9) * L_ + l) * MID_ + (nn & 511)];
    }
    return gW1[(size_t)l * HID_ + (n - 2 * K_ * MID_)];
}
__global__ void packB_kernel(const float* __restrict__ aW1,
                             const float* __restrict__ aW2,
                             const float* __restrict__ gW1) {
    int cid = blockIdx.x * 256 + threadIdx.x;
    int ln = cid & 31;
    int b = cid >> 5;
    int kc = b & (KCDD - 1);
    int nt = b >> 7;
    bool lo = kc >= 64;
    int l0 = (kc & 63) * 16 + (ln & 3) * 2;
    int n0 = nt * 16 + (ln >> 2);
    int n1 = n0 + 8;
    __half h[8];
    h[0] = cvt_split(fetchW(aW1, aW2, gW1, l0,     n0), lo);
    h[1] = cvt_split(fetchW(aW1, aW2, gW1, l0 + 1, n0), lo);
    h[2] = cvt_split(fetchW(aW1, aW2, gW1, l0 + 8, n0), lo);
    h[3] = cvt_split(fetchW(aW1, aW2, gW1, l0 + 9, n0), lo);
    h[4] = cvt_split(fetchW(aW1, aW2, gW1, l0,     n1), lo);
    h[5] = cvt_split(fetchW(aW1, aW2, gW1, l0 + 1, n1), lo);
    h[6] = cvt_split(fetchW(aW1, aW2, gW1, l0 + 8, n1), lo);
    h[7] = cvt_split(fetchW(aW1, aW2, gW1, l0 + 9, n1), lo);
    g_Bh[cid] = *(uint4*)h;
}

/* ------------------ big GEMM: fused B-hi reuse pipeline ----------- */
struct IssueCtx { uint32_t sb; int mtB, ntB, tid; };

__device__ __forceinline__ void issue_A(uint32_t dst, int mtB, int akc, int tid) {
#pragma unroll
    for (int i = 0; i < 4; i++) {
        int cid = tid + i * 256;
        int ln = cid & 31, bb = cid >> 5;
        int kci = bb >> 3, mti = bb & 7;
        uint32_t sa = dst + (uint32_t)(((kci * 8 + mti) * 32 + ln) * 16);
        const uint4* ga = g_Ah + ((size_t)(mtB + mti) * KCDD + akc + kci) * 32 + ln;
        cpa16(sa, ga);
    }
}
__device__ __forceinline__ void issue_B(uint32_t dst, int ntB, int bkc, int tid) {
#pragma unroll
    for (int i = 0; i < 8; i++) {
        int cid = tid + i * 256;
        int ln = cid & 31, bb = cid >> 5;
        int kci = bb >> 4, nti = bb & 15;
        uint32_t sbb = dst + (uint32_t)(((kci * 16 + nti) * 32 + ln) * 16);
        const uint4* gb = g_Bh + ((size_t)(ntB + nti) * KCDD + bkc + kci) * 32 + ln;
        cpa16(sbb, gb);
    }
}
__device__ __forceinline__ void issue_stage2(const IssueCtx& cx, int s) {
    uint32_t base = cx.sb + (uint32_t)(s % 3) * STG2;
    if (s < 16) {
        /* fused: A-hi, A-lo, B-hi */
        issue_A(base,         cx.mtB, s * 4,      cx.tid);
        issue_A(base + 16384, cx.mtB, 64 + s * 4, cx.tid);
        issue_B(base + 32768, cx.ntB, s * 4,      cx.tid);
    } else {
        /* plain: A-hi, B-lo */
        int t = s - 16;
        issue_A(base,         cx.mtB, t * 4,      cx.tid);
        issue_B(base + 32768, cx.ntB, 64 + t * 4, cx.tid);
    }
    asm volatile("cp.async.commit_group;" ::: "memory");
}

__global__ void __launch_bounds__(256, 1) gemm_kernel() {
    extern __shared__ char smem[];
    const uint32_t sb = smem_u32(smem);
    const int tid = threadIdx.x;
    const int lane = tid & 31;
    const int wid = tid >> 5;
    const int wm = wid & 1;
    const int wn = wid >> 1;
    const int mtB = blockIdx.y * 8;
    const int ntB = blockIdx.x * 16;

    IssueCtx cx{sb, mtB, ntB, tid};

    float acc[4][8][4];
#pragma unroll
    for (int a = 0; a < 4; a++)
#pragma unroll
        for (int bq = 0; bq < 8; bq++)
#pragma unroll
            for (int c = 0; c < 4; c++) acc[a][bq][c] = 0.f;

    issue_stage2(cx, 0);
    issue_stage2(cx, 1);
    issue_stage2(cx, 2);

    for (int s = 0; s < NSTG2; s++) {
        asm volatile("cp.async.wait_group 2;" ::: "memory");
        __syncthreads();

        uint32_t base = sb + (uint32_t)(s % 3) * STG2;
        const bool fused = (s < 16);
#pragma unroll
        for (int kc = 0; kc < 4; kc++) {
            uint32_t af[4][4], bf[4][4];
#pragma unroll
            for (int ni = 0; ni < 4; ni++)
                lds128(bf[ni], base + 32768 +
                               (uint32_t)((((kc * 16) + wn * 4 + ni) * 32 + lane) * 16));
#pragma unroll
            for (int mi = 0; mi < 4; mi++)
                lds128(af[mi], base + (uint32_t)((((kc * 8) + wm * 4 + mi) * 32 + lane) * 16));
#pragma unroll
            for (int mi = 0; mi < 4; mi++)
#pragma unroll
                for (int ni = 0; ni < 4; ni++) {
                    mma_f16(acc[mi][ni * 2],     af[mi], bf[ni][0], bf[ni][1]);
                    mma_f16(acc[mi][ni * 2 + 1], af[mi], bf[ni][2], bf[ni][3]);
                }
            if (fused) {
                /* second A set (A-lo) against same B-hi fragments */
#pragma unroll
                for (int mi = 0; mi < 4; mi++)
                    lds128(af[mi], base + 16384 +
                                   (uint32_t)((((kc * 8) + wm * 4 + mi) * 32 + lane) * 16));
#pragma unroll
                for (int mi = 0; mi < 4; mi++)
#pragma unroll
                    for (int ni = 0; ni < 4; ni++) {
                        mma_f16(acc[mi][ni * 2],     af[mi], bf[ni][0], bf[ni][1]);
                        mma_f16(acc[mi][ni * 2 + 1], af[mi], bf[ni][2], bf[ni][3]);
                    }
            }
        }
        __syncthreads();   /* all warps done with buffer s%3 before refill */
        if (s + 3 < NSTG2) issue_stage2(cx, s + 3);
        else asm volatile("cp.async.commit_group;" ::: "memory");
    }

    /* epilogue: streaming stores (evict-first) — keep B resident in L2 */
    const int rBase = blockIdx.y * TM + wm * 64 + (lane >> 2);
    const int cBase = blockIdx.x * TN + wn * 64 + (lane & 3) * 2;
#pragma unroll
    for (int mi = 0; mi < 4; mi++) {
#pragma unroll
        for (int ni = 0; ni < 8; ni++) {
            int row = rBase + mi * 16;
            int col = cBase + ni * 8;
            stcs2(g_Y + (size_t)row * NBIG + col,
                  make_float2(acc[mi][ni][0], acc[mi][ni][1]));
            stcs2(g_Y + (size_t)(row + 8) * NBIG + col,
                  make_float2(acc[mi][ni][2], acc[mi][ni][3]));
        }
    }
}

/* ------------------------------------------------------------------ */
/* score_kernel (R13 winner — 99 us)                                  */
/* ------------------------------------------------------------------ */
__global__ void __launch_bounds__(320) score_kernel(
    const float* __restrict__ ab1, const float* __restrict__ ab2,
    const float* __restrict__ linW, const float* __restrict__ linb) {
    const int b = blockIdx.x;
    const int tid = threadIdx.x;
    const int lane = tid & 31;
    const int w = tid >> 5;
    const int k = w >> 1;
    const int half = w & 1;
    const float* Yb = g_Y + (size_t)b * C_ * NBIG;
    const int off = k * MID_ + half * 256;

    __shared__ float s_part[10][36];
    __shared__ float s_sc[K_ * 36];
    __shared__ float s_l[36];

    float b1r[8], b2r[8];
#pragma unroll
    for (int it = 0; it < 2; it++) {
        float4 v1 = *(const float4*)(ab1 + off + it * 128 + lane * 4);
        float4 v2 = *(const float4*)(ab2 + off + it * 128 + lane * 4);
        b1r[it*4] = v1.x; b1r[it*4+1] = v1.y; b1r[it*4+2] = v1.z; b1r[it*4+3] = v1.w;
        b2r[it*4] = v2.x; b2r[it*4+1] = v2.y; b2r[it*4+2] = v2.z; b2r[it*4+3] = v2.w;
    }

    float kv[6][8];
#pragma unroll
    for (int d = 0; d < 6; d++) {
        const float* kp = Yb + (size_t)d * NBIG + K_ * MID_ + off;
#pragma unroll
        for (int it = 0; it < 2; it++) {
            float4 v = ldcs4(kp + it * 128 + lane * 4);
            kv[d][it*4]   = v.x + b2r[it*4];
            kv[d][it*4+1] = v.y + b2r[it*4+1];
            kv[d][it*4+2] = v.z + b2r[it*4+2];
            kv[d][it*4+3] = v.w + b2r[it*4+3];
        }
    }

#pragma unroll
    for (int c = 0; c < 6; c++) {
        float q[8];
        const float* qp = Yb + (size_t)c * NBIG + off;
#pragma unroll
        for (int it = 0; it < 2; it++) {
            float4 v = ldcs4(qp + it * 128 + lane * 4);
            q[it*4]   = v.x + b1r[it*4];
            q[it*4+1] = v.y + b1r[it*4+1];
            q[it*4+2] = v.z + b1r[it*4+2];
            q[it*4+3] = v.w + b1r[it*4+3];
        }
        float acc[6];
#pragma unroll
        for (int d = 0; d < 6; d++) {
            float a = 0.f;
#pragma unroll
            for (int m = 0; m < 8; m++) a += q[m] * kv[d][m];
            acc[d] = a;
        }
#pragma unroll
        for (int o = 16; o; o >>= 1)
#pragma unroll
            for (int d = 0; d < 6; d++) acc[d] += __shfl_xor_sync(0xffffffffu, acc[d], o);
        if (lane == 0)
#pragma unroll
            for (int d = 0; d < 6; d++) s_part[w][c * 6 + d] = acc[d];
    }
    __syncthreads();

    if (tid < 30) {
        int k2 = tid / 6, c = tid - k2 * 6;
        float v[6];
#pragma unroll
        for (int d = 0; d < 6; d++)
            v[d] = s_part[k2 * 2][c * 6 + d] + s_part[k2 * 2 + 1][c * 6 + d];
        float mx = v[0];
#pragma unroll
        for (int d = 1; d < 6; d++) mx = fmaxf(mx, v[d]);
        float e[6], sum = 0.f;
#pragma unroll
        for (int d = 0; d < 6; d++) { e[d] = expf(v[d] - mx); sum += e[d]; }
        float inv = 1.f / sum;
#pragma unroll
        for (int d = 0; d < 6; d++) s_sc[k2 * 36 + c * 6 + d] = e[d] * inv;
    }
    __syncthreads();

    if (tid < 36) {
        int c = tid / 6, e = tid - (tid / 6) * 6;
        float acc = linb[e];
#pragma unroll
        for (int k2 = 0; k2 < K_; k2++)
#pragma unroll
            for (int d = 0; d < 6; d++)
                acc += s_sc[k2 * 36 + c * 6 + d] * linW[(k2 * 6 + d) * 6 + e];
        s_l[tid] = acc;
    }
    __syncthreads();

    if (tid < 6) {
        float* r = s_l + tid * 6;
        float mx = r[0];
#pragma unroll
        for (int e = 1; e < 6; e++) mx = fmaxf(mx, r[e]);
        float ev[6], sum = 0.f;
#pragma unroll
        for (int e = 0; e < 6; e++) { ev[e] = expf(r[e] - mx); sum += ev[e]; }
        float inv = 1.f / sum;
        float* ap = g_A + (size_t)b * 36 + tid * 6;
#pragma unroll
        for (int e = 0; e < 6; e++) ap[e] = ev[e] * inv;
    }
}

/* ------------------------------------------------------------------ */
/* h_kernel (R13 winner)                                              */
/* ------------------------------------------------------------------ */
__global__ void __launch_bounds__(256) h_kernel(
    const float* __restrict__ gb1, const float* __restrict__ prelu_a,
    const float* __restrict__ bn1g, const float* __restrict__ bn1b,
    const float* __restrict__ bn1m, const float* __restrict__ bn1v) {
    int idx = blockIdx.x * 256 + threadIdx.x;
    int j4 = idx & 127;
    int r = idx >> 7;
    int b = r / 6;
    int c = r - b * 6;
    const float* Ab = g_A + (size_t)b * 36 + c * 6;
    float a0 = Ab[0], a1 = Ab[1], a2 = Ab[2], a3 = Ab[3], a4 = Ab[4], a5 = Ab[5];
    const float* xg = g_Y + (size_t)b * 6 * NBIG + 2 * K_ * MID_ + j4 * 4;
    float4 z = *(const float4*)(gb1 + j4 * 4);
    float4 v;
#define ACC4(aa, d) \
    v = ldcs4(xg + (size_t)(d) * NBIG); \
    z.x += (aa) * v.x; z.y += (aa) * v.y; z.z += (aa) * v.z; z.w += (aa) * v.w;
    ACC4(a0, 0) ACC4(a1, 1) ACC4(a2, 2) ACC4(a3, 3) ACC4(a4, 4) ACC4(a5, 5)
#undef ACC4
    float pa = prelu_a[0];
    z.x = z.x >= 0.f ? z.x : pa * z.x;
    z.y = z.y >= 0.f ? z.y : pa * z.y;
    z.z = z.z >= 0.f ? z.z : pa * z.z;
    z.w = z.w >= 0.f ? z.w : pa * z.w;
    float inv = bn1g[c] * (1.f / sqrtf(bn1v[c] + 1e-5f));
    float mu = bn1m[c], bb = bn1b[c];
    z.x = (z.x - mu) * inv + bb;
    z.y = (z.y - mu) * inv + bb;
    z.z = (z.z - mu) * inv + bb;
    z.w = (z.w - mu) * inv + bb;
    *(float4*)(g_H + (size_t)r * HID_ + j4 * 4) = z;
}

/* ------------------------------------------------------------------ */
#define SBM 128
#define SBN 128
#define SBK 16
__global__ void __launch_bounds__(256, 2) hg_gemm_kernel(const float* __restrict__ gW2) {
    __shared__ float As[SBK][SBM];
    __shared__ float Bs[SBK][SBN];
    const int bx = blockIdx.x;
    const int by = blockIdx.y;
    const int tid = threadIdx.x;
    const int tx = tid & 15;
    const int ty = tid >> 4;
    const int a_row = tid >> 2;
    const int a_col = (tid & 3) << 2;
    const int b_row = tid >> 5;
    const int b_col = (tid & 31) << 2;
    const float* Ab = g_H + (size_t)(by * SBM) * HID_;
    const float* Bb = gW2 + bx * SBN;

    float acc[8][8];
#pragma unroll
    for (int i = 0; i < 8; i++)
#pragma unroll
        for (int j = 0; j < 8; j++) acc[i][j] = 0.f;

    for (int k0 = 0; k0 < HID_; k0 += SBK) {
#pragma unroll
        for (int i = 0; i < 2; i++) {
            int r = a_row + i * 64;
            float4 v = *(const float4*)(Ab + (size_t)r * HID_ + k0 + a_col);
            As[a_col + 0][r] = v.x;
            As[a_col + 1][r] = v.y;
            As[a_col + 2][r] = v.z;
            As[a_col + 3][r] = v.w;
        }
#pragma unroll
        for (int i = 0; i < 2; i++) {
            int r = b_row + i * 8;
            *(float4*)&Bs[r][b_col] =
                *(const float4*)(Bb + (size_t)(k0 + r) * OUT_ + b_col);
        }
        __syncthreads();
#pragma unroll
        for (int kk = 0; kk < SBK; kk++) {
            float4 a0 = *(const float4*)&As[kk][ty * 8];
            float4 a1 = *(const float4*)&As[kk][ty * 8 + 4];
            float4 b0 = *(const float4*)&Bs[kk][tx * 8];
            float4 b1 = *(const float4*)&Bs[kk][tx * 8 + 4];
            float ar[8] = {a0.x, a0.y, a0.z, a0.w, a1.x, a1.y, a1.z, a1.w};
            float br[8] = {b0.x, b0.y, b0.z, b0.w, b1.x, b1.y, b1.z, b1.w};
#pragma unroll
            for (int i = 0; i < 8; i++)
#pragma unroll
                for (int j = 0; j < 8; j++) acc[i][j] += ar[i] * br[j];
        }
        __syncthreads();
    }
    float* Cp = g_HG + (size_t)(by * SBM + ty * 8) * OUT_ + bx * SBN + tx * 8;
#pragma unroll
    for (int i = 0; i < 8; i++)
#pragma unroll
        for (int j = 0; j < 8; j += 4)
            *(float4*)(Cp + (size_t)i * OUT_ + j) =
                make_float4(acc[i][j], acc[i][j+1], acc[i][j+2], acc[i][j+3]);
}

/* ------------------------------------------------------------------ */
__global__ void __launch_bounds__(256) out_kernel(
    const float* __restrict__ gb2,
    const float* __restrict__ bn2g, const float* __restrict__ bn2b,
    const float* __restrict__ bn2m, const float* __restrict__ bn2v,
    float* __restrict__ out) {
    const int b = blockIdx.x;
    const int o = threadIdx.x;
    __shared__ float sA[36];
    if (o < 36) sA[o] = g_A[(size_t)b * 36 + o];
    __syncthreads();
    float hgv[6];
#pragma unroll
    for (int d = 0; d < 6; d++)
        hgv[d] = __ldcs(&g_HG[((size_t)b * 6 + d) * OUT_ + o]);
    float g2 = gb2[o];
#pragma unroll
    for (int c = 0; c < 6; c++) {
        float acc = g2;
#pragma unroll
        for (int d = 0; d < 6; d++) acc += sA[c * 6 + d] * hgv[d];
        float inv = bn2g[c] * (1.f / sqrtf(bn2v[c] + 1e-5f));
        acc = (acc - bn2m[c]) * inv + bn2b[c];
        out[((size_t)b * C_ + c) * OUT_ + o] = acc;
    }
}

/* ------------------------------------------------------------------ */
extern "C" void kernel_launch(void* const* d_in, const int* in_sizes, int n_in,
                              void* d_out, int out_size) {
    const float* x       = (const float*)d_in[0];
    const float* aW1     = (const float*)d_in[1];
    const float* ab1     = (const float*)d_in[2];
    const float* aW2     = (const float*)d_in[3];
    const float* ab2     = (const float*)d_in[4];
    const float* linW    = (const float*)d_in[5];
    const float* linb    = (const float*)d_in[6];
    const float* gW1     = (const float*)d_in[7];
    const float* gb1     = (const float*)d_in[8];
    const float* gW2     = (const float*)d_in[9];
    const float* gb2     = (const float*)d_in[10];
    const float* prelu_a = (const float*)d_in[11];
    const float* bn1g    = (const float*)d_in[12];
    const float* bn1b    = (const float*)d_in[13];
    const float* bn1m    = (const float*)d_in[14];
    const float* bn1v    = (const float*)d_in[15];
    const float* bn2g    = (const float*)d_in[16];
    const float* bn2b    = (const float*)d_in[17];
    const float* bn2m    = (const float*)d_in[18];
    const float* bn2v    = (const float*)d_in[19];
    float* out = (float*)d_out;

    static bool attr_set = false;
    if (!attr_set) {
        cudaFuncSetAttribute(gemm_kernel,
                             cudaFuncAttributeMaxDynamicSharedMemorySize, SMEM_TOTAL2);
        attr_set = true;
    }

    packA_kernel<<<(MROWS / 16) * KCDD * 32 / 256, 256>>>(x);
    packB_kernel<<<(NBIG / 16) * KCDD * 32 / 256, 256>>>(aW1, aW2, gW1);

    dim3 grid(NBIG / TN, MROWS / TM);   /* 22 x 192 */
    gemm_kernel<<<grid, 256, SMEM_TOTAL2>>>();

    score_kernel<<<B_, 320>>>(ab1, ab2, linW, linb);
    h_kernel<<<MROWS * (HID_ / 4) / 256, 256>>>(gb1, prelu_a, bn1g, bn1b, bn1m, bn1v);
    {
        dim3 g2(OUT_ / SBN, MROWS / SBM);
        hg_gemm_kernel<<<g2, 256>>>(gW2);
    }
    out_kernel<<<B_, OUT_>>>(gb2, bn2g, bn2b, bn2m, bn2v, out);
}